// round 1
// baseline (speedup 1.0000x reference)
#include <cuda_runtime.h>
#include <math.h>

#define H     1024
#define NEXP  8
#define MAXT  8192
#define MAXROWS (MAXT * 2)

#define BM 128
#define BN 128
#define BK 16

// ---------------- scratch (device globals; no runtime allocation) ----------------
__device__ float g_bufA[(size_t)MAXROWS * H];   // 64 MiB: layer1 output
__device__ float g_bufB[(size_t)MAXROWS * H];   // 64 MiB: layer2 output
__device__ int   g_cnt[NEXP];
__device__ int   g_off[NEXP];
__device__ int   g_fill[NEXP];
__device__ int   g_row_tok[MAXROWS];   // gathered row -> token index
__device__ float g_row_w[MAXROWS];     // gathered row -> combine weight
__device__ int   g_tok_e[MAXROWS];     // per (token,k): expert
__device__ float g_tok_w[MAXROWS];     // per (token,k): weight

// ---------------- tiny setup kernels ----------------
__global__ void k_init() {
    int i = threadIdx.x;
    if (i < NEXP) g_cnt[i] = 0;
}

__global__ void k_zero(float* __restrict__ p, long n4) {
    // zero n4 float4's
    long i = (long)blockIdx.x * blockDim.x + threadIdx.x;
    long stride = (long)gridDim.x * blockDim.x;
    float4 z = make_float4(0.f, 0.f, 0.f, 0.f);
    for (; i < n4; i += stride) reinterpret_cast<float4*>(p)[i] = z;
}

__global__ void k_offsets() {
    if (threadIdx.x == 0) {
        int s = 0;
        for (int e = 0; e < NEXP; e++) {
            g_off[e] = s;
            s += g_cnt[e];
            g_fill[e] = 0;
        }
    }
}

__global__ void k_scatter(int T) {
    int i = blockIdx.x * blockDim.x + threadIdx.x;
    if (i >= 2 * T) return;
    int e = g_tok_e[i];
    int pos = g_off[e] + atomicAdd(&g_fill[e], 1);
    g_row_tok[pos] = i >> 1;      // token index
    g_row_w[pos]   = g_tok_w[i];
}

// ---------------- router: logits, softmax top-2, renormalized weights ----------------
__global__ void k_router(const float* __restrict__ x,
                         const float* __restrict__ gw,
                         const float* __restrict__ gb,
                         float* __restrict__ logits_out,   // may be null
                         int T)
{
    int warp = (blockIdx.x * blockDim.x + threadIdx.x) >> 5;
    int lane = threadIdx.x & 31;
    if (warp >= T) return;
    const float* xr = x + (size_t)warp * H;

    float acc[NEXP];
#pragma unroll
    for (int e = 0; e < NEXP; e++) acc[e] = 0.f;

    for (int h = lane; h < H; h += 32) {
        float xv = __ldg(xr + h);
        const float4* g = reinterpret_cast<const float4*>(gw + (size_t)h * NEXP);
        float4 a = __ldg(g);
        float4 b = __ldg(g + 1);
        acc[0] += xv * a.x; acc[1] += xv * a.y; acc[2] += xv * a.z; acc[3] += xv * a.w;
        acc[4] += xv * b.x; acc[5] += xv * b.y; acc[6] += xv * b.z; acc[7] += xv * b.w;
    }
#pragma unroll
    for (int e = 0; e < NEXP; e++)
#pragma unroll
        for (int o = 16; o > 0; o >>= 1)
            acc[e] += __shfl_xor_sync(0xffffffffu, acc[e], o);

    if (lane == 0) {
        float lg[NEXP];
#pragma unroll
        for (int e = 0; e < NEXP; e++) {
            lg[e] = acc[e] + gb[e];
            if (logits_out) logits_out[(size_t)warp * NEXP + e] = lg[e];
        }
        // top-2 on logits (softmax is monotone); ties -> lowest index (matches lax.top_k)
        int i1 = 0;
#pragma unroll
        for (int e = 1; e < NEXP; e++) if (lg[e] > lg[i1]) i1 = e;
        int i2 = (i1 == 0) ? 1 : 0;
#pragma unroll
        for (int e = 0; e < NEXP; e++) {
            if (e == i1) continue;
            if (lg[e] > lg[i2]) i2 = e;
        }
        // renormalized top-2 softmax weights
        float p2 = expf(lg[i2] - lg[i1]);
        float inv = 1.f / (1.f + p2);
        float w1 = inv;
        float w2 = p2 * inv;

        g_tok_e[warp * 2 + 0] = i1;
        g_tok_w[warp * 2 + 0] = w1;
        g_tok_e[warp * 2 + 1] = i2;
        g_tok_w[warp * 2 + 1] = w2;
        atomicAdd(&g_cnt[i1], 1);
        atomicAdd(&g_cnt[i2], 1);
    }
}

// ---------------- gathered expert GEMM ----------------
// LAYER 1: A = x gathered by g_row_tok, C = g_bufA, relu
// LAYER 2: A = g_bufA,                  C = g_bufB, relu
// LAYER 3: A = g_bufB,                  C = d_out via weighted atomic scatter, no relu
template <int LAYER>
__global__ __launch_bounds__(256, 2)
void k_gemm(const float* __restrict__ xin,    // used when LAYER==1
            const float* __restrict__ W,      // [E][H][H] row-major (K x N per expert)
            const float* __restrict__ Bias,   // [E][H]
            float* __restrict__ outp,         // used when LAYER==3
            int T)
{
    int e = blockIdx.z;
    int cnt = g_cnt[e];
    int row0 = blockIdx.y * BM;
    if (row0 >= cnt) return;
    int base = g_off[e];
    const float* We = W + (size_t)e * H * H;
    const float* be = Bias + (size_t)e * H;
    int col0 = blockIdx.x * BN;
    int tid = threadIdx.x;
    int ty = tid >> 4, tx = tid & 15;

    const float* Ain;
    if (LAYER == 1)      Ain = xin;      // indirect rows
    else if (LAYER == 2) Ain = g_bufA;
    else                 Ain = g_bufB;

    __shared__ float As[BK][BM];
    __shared__ float Bs[BK][BN];

    // per-thread A row pointers for its two load slots
    const float* aptr[2];
    bool avalid[2];
#pragma unroll
    for (int i = 0; i < 2; i++) {
        int idx = tid + i * 256;           // [0,512)
        int arow = idx >> 2;               // 0..127
        int grow = row0 + arow;
        avalid[i] = (grow < cnt);
        if (avalid[i]) {
            if (LAYER == 1) {
                int tok = g_row_tok[base + grow];
                aptr[i] = Ain + (size_t)tok * H;
            } else {
                aptr[i] = Ain + (size_t)(base + grow) * H;
            }
        } else {
            aptr[i] = Ain;  // unread (predicated load)
        }
    }

    float acc[8][8];
#pragma unroll
    for (int i = 0; i < 8; i++)
#pragma unroll
        for (int j = 0; j < 8; j++) acc[i][j] = 0.f;

    for (int kt = 0; kt < H; kt += BK) {
        // load A tile (transpose into As[k][m])
#pragma unroll
        for (int i = 0; i < 2; i++) {
            int idx = tid + i * 256;
            int arow = idx >> 2;
            int k4 = (idx & 3) << 2;
            float4 v = avalid[i] ? *reinterpret_cast<const float4*>(aptr[i] + kt + k4)
                                 : make_float4(0.f, 0.f, 0.f, 0.f);
            As[k4 + 0][arow] = v.x;
            As[k4 + 1][arow] = v.y;
            As[k4 + 2][arow] = v.z;
            As[k4 + 3][arow] = v.w;
        }
        // load B tile
#pragma unroll
        for (int i = 0; i < 2; i++) {
            int idx = tid + i * 256;
            int brow = idx >> 5;              // 0..15
            int bc = (idx & 31) << 2;         // 0..124
            *reinterpret_cast<float4*>(&Bs[brow][bc]) =
                *reinterpret_cast<const float4*>(We + (size_t)(kt + brow) * H + col0 + bc);
        }
        __syncthreads();

#pragma unroll
        for (int k = 0; k < BK; k++) {
            float a[8], b[8];
            *reinterpret_cast<float4*>(&a[0]) = *reinterpret_cast<const float4*>(&As[k][ty * 4]);
            *reinterpret_cast<float4*>(&a[4]) = *reinterpret_cast<const float4*>(&As[k][64 + ty * 4]);
            *reinterpret_cast<float4*>(&b[0]) = *reinterpret_cast<const float4*>(&Bs[k][tx * 4]);
            *reinterpret_cast<float4*>(&b[4]) = *reinterpret_cast<const float4*>(&Bs[k][64 + tx * 4]);
#pragma unroll
            for (int i = 0; i < 8; i++)
#pragma unroll
                for (int j = 0; j < 8; j++)
                    acc[i][j] += a[i] * b[j];
        }
        __syncthreads();
    }

    // bias registers (cols: tx*4..+3 and 64+tx*4..+3)
    float bj[8];
    *reinterpret_cast<float4*>(&bj[0]) = *reinterpret_cast<const float4*>(be + col0 + tx * 4);
    *reinterpret_cast<float4*>(&bj[4]) = *reinterpret_cast<const float4*>(be + col0 + 64 + tx * 4);

#pragma unroll
    for (int i = 0; i < 8; i++) {
        int lrow = (i < 4) ? (ty * 4 + i) : (64 + ty * 4 + (i - 4));
        int grow = row0 + lrow;
        if (grow >= cnt) continue;

        if (LAYER == 3) {
            int tok = g_row_tok[base + grow];
            float w = g_row_w[base + grow];
            float* orow = outp + (size_t)tok * H + col0;
#pragma unroll
            for (int j = 0; j < 8; j++) {
                int lcol = (j < 4) ? (tx * 4 + j) : (64 + tx * 4 + (j - 4));
                atomicAdd(orow + lcol, w * (acc[i][j] + bj[j]));
            }
        } else {
            float* crow = ((LAYER == 1) ? g_bufA : g_bufB) + (size_t)(base + grow) * H + col0;
            float4 v0, v1;
            v0.x = fmaxf(acc[i][0] + bj[0], 0.f);
            v0.y = fmaxf(acc[i][1] + bj[1], 0.f);
            v0.z = fmaxf(acc[i][2] + bj[2], 0.f);
            v0.w = fmaxf(acc[i][3] + bj[3], 0.f);
            v1.x = fmaxf(acc[i][4] + bj[4], 0.f);
            v1.y = fmaxf(acc[i][5] + bj[5], 0.f);
            v1.z = fmaxf(acc[i][6] + bj[6], 0.f);
            v1.w = fmaxf(acc[i][7] + bj[7], 0.f);
            *reinterpret_cast<float4*>(crow + tx * 4)      = v0;
            *reinterpret_cast<float4*>(crow + 64 + tx * 4) = v1;
        }
    }
}

// ---------------- launch ----------------
extern "C" void kernel_launch(void* const* d_in, const int* in_sizes, int n_in,
                              void* d_out, int out_size)
{
    const float* x  = (const float*)d_in[0];
    const float* gw = (const float*)d_in[1];
    const float* gb = (const float*)d_in[2];
    const float* w1 = (const float*)d_in[3];
    const float* b1 = (const float*)d_in[4];
    const float* w2 = (const float*)d_in[5];
    const float* b2 = (const float*)d_in[6];
    const float* w3 = (const float*)d_in[7];
    const float* b3 = (const float*)d_in[8];
    float* out = (float*)d_out;

    int T = in_sizes[0] / H;                 // 8192
    if (T > MAXT) T = MAXT;                  // safety clamp (shapes are fixed)
    long outN = (long)T * H;
    bool has_logits = ((long)out_size >= outN + (long)T * NEXP);
    float* logits = has_logits ? out + outN : nullptr;

    k_init<<<1, 32>>>();
    k_zero<<<2048, 256>>>(out, outN / 4);
    k_router<<<(T * 32 + 255) / 256, 256>>>(x, gw, gb, logits, T);
    k_offsets<<<1, 32>>>();
    k_scatter<<<(2 * T + 255) / 256, 256>>>(T);

    dim3 grid(H / BN, (T + BM - 1) / BM, NEXP);
    k_gemm<1><<<grid, 256>>>(x,       w1, b1, nullptr, T);
    k_gemm<2><<<grid, 256>>>(nullptr, w2, b2, nullptr, T);
    k_gemm<3><<<grid, 256>>>(nullptr, w3, b3, out,     T);
}

// round 3
// speedup vs baseline: 1.8000x; 1.8000x over previous
#include <cuda_runtime.h>
#include <cuda_bf16.h>
#include <math.h>
#include <stdint.h>

#define H     1024
#define NEXP  8
#define MAXT  8192
#define MAXROWS (MAXT * 2)

#define BK      32
#define NK      (H / BK)      // 32 k-tiles
#define TILE_M  128
#define TILE_N  128
#define NSTAGE  3

// SMEM stage layout: 4 buffers of 128 rows x 80B (32 bf16 + 8 pad)
#define ROWB        80
#define BUF_BYTES   (128 * ROWB)        // 10240
#define OFF_AHI     0
#define OFF_ALO     (1 * BUF_BYTES)
#define OFF_BHI     (2 * BUF_BYTES)
#define OFF_BLO     (3 * BUF_BYTES)
#define STAGE_BYTES (4 * BUF_BYTES)     // 40960
#define SMEM_TOTAL  (NSTAGE * STAGE_BYTES)  // 122880

// ---------------- scratch (device globals; no runtime allocation) ----------------
__device__ float g_bufA[(size_t)MAXROWS * H];                     // 64 MiB (layer3 partials)
__device__ __nv_bfloat16 g_a1hi[(size_t)MAXROWS * H];             // 32 MiB
__device__ __nv_bfloat16 g_a1lo[(size_t)MAXROWS * H];
__device__ __nv_bfloat16 g_a2hi[(size_t)MAXROWS * H];
__device__ __nv_bfloat16 g_a2lo[(size_t)MAXROWS * H];
__device__ __nv_bfloat16 g_xhi[(size_t)MAXT * H];                 // 16 MiB
__device__ __nv_bfloat16 g_xlo[(size_t)MAXT * H];
__device__ __nv_bfloat16 g_wthi[(size_t)3 * NEXP * H * H];        // 48 MiB, [l][e][n][k]
__device__ __nv_bfloat16 g_wtlo[(size_t)3 * NEXP * H * H];
__device__ int   g_cnt[NEXP];
__device__ int   g_off[NEXP];
__device__ int   g_fill[NEXP];
__device__ int   g_row_tok[MAXROWS];
__device__ float g_row_w[MAXROWS];
__device__ int   g_tok_e[MAXROWS];
__device__ float g_tok_w[MAXROWS];
__device__ int   g_tok_pos[MAXROWS];

// ---------------- helpers ----------------
__device__ __forceinline__ uint32_t smem_u32(const void* p) {
    uint32_t a;
    asm("{ .reg .u64 t; cvta.to.shared.u64 t, %1; cvt.u32.u64 %0, t; }" : "=r"(a) : "l"(p));
    return a;
}
__device__ __forceinline__ void cp16(uint32_t dst, const void* src, uint32_t sz) {
    asm volatile("cp.async.cg.shared.global [%0], [%1], 16, %2;"
                 :: "r"(dst), "l"(src), "r"(sz) : "memory");
}
__device__ __forceinline__ void cp_commit() { asm volatile("cp.async.commit_group;" ::: "memory"); }
template <int N>
__device__ __forceinline__ void cp_wait() { asm volatile("cp.async.wait_group %0;" :: "n"(N) : "memory"); }

__device__ __forceinline__ void mma_bf16(float* d, const uint32_t* a, const uint32_t* b) {
    asm volatile("mma.sync.aligned.m16n8k16.row.col.f32.bf16.bf16.f32 "
        "{%0,%1,%2,%3}, {%4,%5,%6,%7}, {%8,%9}, {%0,%1,%2,%3};"
        : "+f"(d[0]), "+f"(d[1]), "+f"(d[2]), "+f"(d[3])
        : "r"(a[0]), "r"(a[1]), "r"(a[2]), "r"(a[3]), "r"(b[0]), "r"(b[1]));
}
__device__ __forceinline__ uint32_t pk(__nv_bfloat16 a, __nv_bfloat16 b) {
    __nv_bfloat162 t = __halves2bfloat162(a, b);
    return *reinterpret_cast<uint32_t*>(&t);
}
__device__ __forceinline__ void split1(float v, __nv_bfloat16& h, __nv_bfloat16& l) {
    h = __float2bfloat16(v);
    l = __float2bfloat16(v - __bfloat162float(h));
}

// ---------------- tiny setup kernels ----------------
__global__ void k_init() { if (threadIdx.x < NEXP) g_cnt[threadIdx.x] = 0; }

__global__ void k_offsets() {
    if (threadIdx.x == 0) {
        int s = 0;
        for (int e = 0; e < NEXP; e++) { g_off[e] = s; s += g_cnt[e]; g_fill[e] = 0; }
    }
}

__global__ void k_scatter(int T) {
    int i = blockIdx.x * blockDim.x + threadIdx.x;
    if (i >= 2 * T) return;
    int e = g_tok_e[i];
    int pos = g_off[e] + atomicAdd(&g_fill[e], 1);
    g_row_tok[pos] = i >> 1;
    g_row_w[pos]   = g_tok_w[i];
    g_tok_pos[i]   = pos;
}

// ---------------- router ----------------
__global__ void k_router(const float* __restrict__ x, const float* __restrict__ gw,
                         const float* __restrict__ gb, float* __restrict__ logits_out, int T) {
    int warp = (blockIdx.x * blockDim.x + threadIdx.x) >> 5;
    int lane = threadIdx.x & 31;
    if (warp >= T) return;
    const float* xr = x + (size_t)warp * H;

    float acc[NEXP];
#pragma unroll
    for (int e = 0; e < NEXP; e++) acc[e] = 0.f;
    for (int h = lane; h < H; h += 32) {
        float xv = __ldg(xr + h);
        const float4* g = reinterpret_cast<const float4*>(gw + (size_t)h * NEXP);
        float4 a = __ldg(g); float4 b = __ldg(g + 1);
        acc[0] += xv * a.x; acc[1] += xv * a.y; acc[2] += xv * a.z; acc[3] += xv * a.w;
        acc[4] += xv * b.x; acc[5] += xv * b.y; acc[6] += xv * b.z; acc[7] += xv * b.w;
    }
#pragma unroll
    for (int e = 0; e < NEXP; e++)
#pragma unroll
        for (int o = 16; o > 0; o >>= 1)
            acc[e] += __shfl_xor_sync(0xffffffffu, acc[e], o);

    if (lane == 0) {
        float lg[NEXP];
#pragma unroll
        for (int e = 0; e < NEXP; e++) {
            lg[e] = acc[e] + gb[e];
            if (logits_out) logits_out[(size_t)warp * NEXP + e] = lg[e];
        }
        int i1 = 0;
#pragma unroll
        for (int e = 1; e < NEXP; e++) if (lg[e] > lg[i1]) i1 = e;
        int i2 = (i1 == 0) ? 1 : 0;
#pragma unroll
        for (int e = 0; e < NEXP; e++) { if (e == i1) continue; if (lg[e] > lg[i2]) i2 = e; }
        float p2 = expf(lg[i2] - lg[i1]);
        float inv = 1.f / (1.f + p2);
        g_tok_e[warp * 2 + 0] = i1; g_tok_w[warp * 2 + 0] = inv;
        g_tok_e[warp * 2 + 1] = i2; g_tok_w[warp * 2 + 1] = p2 * inv;
        atomicAdd(&g_cnt[i1], 1);
        atomicAdd(&g_cnt[i2], 1);
    }
}

// ---------------- x split: fp32 -> bf16 hi/lo ----------------
__global__ void k_split_x(const float* __restrict__ x, long n) {
    long i = (long)blockIdx.x * blockDim.x + threadIdx.x;
    long stride = (long)gridDim.x * blockDim.x;
    for (; i < n; i += stride) {
        float4 v = reinterpret_cast<const float4*>(x)[i];
        __nv_bfloat16 h0, h1, h2, h3, l0, l1, l2, l3;
        split1(v.x, h0, l0); split1(v.y, h1, l1);
        split1(v.z, h2, l2); split1(v.w, h3, l3);
        reinterpret_cast<uint2*>(g_xhi)[i] = make_uint2(pk(h0, h1), pk(h2, h3));
        reinterpret_cast<uint2*>(g_xlo)[i] = make_uint2(pk(l0, l1), pk(l2, l3));
    }
}

// ---------------- weight transpose + bf16 hi/lo split ----------------
// in:  W [E][K][N] fp32   out: g_wthi/g_wtlo [layer][E][N][K] bf16
__global__ void k_split_w(const float* __restrict__ W, int layer) {
    __shared__ float t[32][33];
    int e = blockIdx.z;
    int kb = blockIdx.y * 32, nb = blockIdx.x * 32;
    const float* We = W + (size_t)e * H * H;
    int tx = threadIdx.x, ty = threadIdx.y;   // 32 x 8
#pragma unroll
    for (int i = 0; i < 32; i += 8)
        t[ty + i][tx] = We[(size_t)(kb + ty + i) * H + nb + tx];
    __syncthreads();
    size_t obase = ((size_t)layer * NEXP + e) * H * H;
    __nv_bfloat16* he = g_wthi + obase;
    __nv_bfloat16* le = g_wtlo + obase;
#pragma unroll
    for (int i = 0; i < 32; i += 8) {
        float v = t[tx][ty + i];
        __nv_bfloat16 h, l; split1(v, h, l);
        he[(size_t)(nb + ty + i) * H + kb + tx] = h;
        le[(size_t)(nb + ty + i) * H + kb + tx] = l;
    }
}

// ---------------- HMMA split-bf16 gathered expert GEMM ----------------
// LAYER 1: A = x (split, gathered) -> relu -> a1 (split)
// LAYER 2: A = a1                  -> relu -> a2 (split)
// LAYER 3: A = a2                  -> w*(acc+bias) -> g_bufA fp32
template <int LAYER>
__global__ __launch_bounds__(256, 1)
void k_gemm_mma(int layer, const float* __restrict__ Bias, int T) {
    int e = blockIdx.z;
    int cnt = g_cnt[e];
    int row0 = blockIdx.y * TILE_M;
    if (row0 >= cnt) return;
    int base = g_off[e];
    int col0 = blockIdx.x * TILE_N;
    int tid = threadIdx.x;
    int wid = tid >> 5, lane = tid & 31;
    int wm = wid & 1, wn = wid >> 1;       // warp tile: rows wm*64, cols wn*32
    int r1 = lane >> 2, cq = lane & 3;

    extern __shared__ char smem[];
    uint32_t sb = smem_u32(smem);

    // ---- per-thread load setup ----
    int lrow = tid >> 1, lhalf = tid & 1;   // 2 threads per row, 32B halves
    int agrow = row0 + lrow;
    bool aval = (agrow < cnt);
    long aridx = 0;
    if (aval) aridx = (LAYER == 1) ? (long)g_row_tok[base + agrow] : (long)(base + agrow);
    const __nv_bfloat16* pAhi;
    const __nv_bfloat16* pAlo;
    if (LAYER == 1)      { pAhi = g_xhi;  pAlo = g_xlo;  }
    else if (LAYER == 2) { pAhi = g_a1hi; pAlo = g_a1lo; }
    else                 { pAhi = g_a2hi; pAlo = g_a2lo; }
    const char* gAhi = (const char*)(pAhi + (size_t)aridx * H) + lhalf * 32;
    const char* gAlo = (const char*)(pAlo + (size_t)aridx * H) + lhalf * 32;
    uint32_t aSz = aval ? 16u : 0u;

    size_t wbase = ((size_t)layer * NEXP + e) * H * H;
    const char* gBhi = (const char*)(g_wthi + wbase + (size_t)(col0 + lrow) * H) + lhalf * 32;
    const char* gBlo = (const char*)(g_wtlo + wbase + (size_t)(col0 + lrow) * H) + lhalf * 32;

    uint32_t sdst = sb + lrow * ROWB + lhalf * 32;

    // ---- accumulators ----
    float acc[4][4][4];
#pragma unroll
    for (int i = 0; i < 4; i++)
#pragma unroll
        for (int j = 0; j < 4; j++)
#pragma unroll
            for (int r = 0; r < 4; r++) acc[i][j][r] = 0.f;

    // ---- pipeline ----
    auto loadStage = [&](int kt) {
        uint32_t st = sdst + (kt % NSTAGE) * STAGE_BYTES;
        long go = (long)kt * 64;           // bytes into row (BK*2)
        cp16(st + OFF_AHI,      gAhi + go,      aSz);
        cp16(st + OFF_AHI + 16, gAhi + go + 16, aSz);
        cp16(st + OFF_ALO,      gAlo + go,      aSz);
        cp16(st + OFF_ALO + 16, gAlo + go + 16, aSz);
        cp16(st + OFF_BHI,      gBhi + go,      16u);
        cp16(st + OFF_BHI + 16, gBhi + go + 16, 16u);
        cp16(st + OFF_BLO,      gBlo + go,      16u);
        cp16(st + OFF_BLO + 16, gBlo + go + 16, 16u);
    };

    loadStage(0); cp_commit();
    loadStage(1); cp_commit();

    // per-thread fragment base offsets (bytes within a stage)
    uint32_t aoff = (uint32_t)((wm * 64 + r1) * ROWB + cq * 4);
    uint32_t boff = (uint32_t)((wn * 32 + r1) * ROWB + cq * 4);

    for (int kt = 0; kt < NK; kt++) {
        cp_wait<1>();
        __syncthreads();
        if (kt + 2 < NK) loadStage(kt + 2);
        cp_commit();

        const char* st = smem + (kt % NSTAGE) * STAGE_BYTES;
        const char* sAh = st + OFF_AHI;
        const char* sAl = st + OFF_ALO;
        const char* sBh = st + OFF_BHI;
        const char* sBl = st + OFF_BLO;

#pragma unroll
        for (int kp = 0; kp < 2; kp++) {
            uint32_t kb = kp * 32;         // byte offset of k-phase
            uint32_t ahi[4][4], alo[4][4], bhi[4][2], blo[4][2];
#pragma unroll
            for (int i = 0; i < 4; i++) {
                uint32_t o = aoff + kb + i * (16 * ROWB);
                ahi[i][0] = *(const uint32_t*)(sAh + o);
                ahi[i][1] = *(const uint32_t*)(sAh + o + 8 * ROWB);
                ahi[i][2] = *(const uint32_t*)(sAh + o + 16);
                ahi[i][3] = *(const uint32_t*)(sAh + o + 8 * ROWB + 16);
                alo[i][0] = *(const uint32_t*)(sAl + o);
                alo[i][1] = *(const uint32_t*)(sAl + o + 8 * ROWB);
                alo[i][2] = *(const uint32_t*)(sAl + o + 16);
                alo[i][3] = *(const uint32_t*)(sAl + o + 8 * ROWB + 16);
            }
#pragma unroll
            for (int j = 0; j < 4; j++) {
                uint32_t o = boff + kb + j * (8 * ROWB);
                bhi[j][0] = *(const uint32_t*)(sBh + o);
                bhi[j][1] = *(const uint32_t*)(sBh + o + 16);
                blo[j][0] = *(const uint32_t*)(sBl + o);
                blo[j][1] = *(const uint32_t*)(sBl + o + 16);
            }
#pragma unroll
            for (int i = 0; i < 4; i++)
#pragma unroll
                for (int j = 0; j < 4; j++) {
                    mma_bf16(acc[i][j], ahi[i], bhi[j]);
                    mma_bf16(acc[i][j], ahi[i], blo[j]);
                    mma_bf16(acc[i][j], alo[i], bhi[j]);
                }
        }
        __syncthreads();
    }

    // ---- epilogue ----
    const float* be = Bias + (size_t)e * H + col0 + wn * 32 + cq * 2;
    float2 bj[4];
#pragma unroll
    for (int j = 0; j < 4; j++) bj[j] = *reinterpret_cast<const float2*>(be + j * 8);

#pragma unroll
    for (int i = 0; i < 4; i++) {
        int ra = wm * 64 + i * 16 + r1;     // local rows
        int rb = ra + 8;
        bool va = (row0 + ra < cnt), vb = (row0 + rb < cnt);
        long oa = (long)(base + row0 + ra) * H;
        long ob = (long)(base + row0 + rb) * H;
        float wa = 0.f, wb = 0.f;
        if (LAYER == 3) {
            if (va) wa = g_row_w[base + row0 + ra];
            if (vb) wb = g_row_w[base + row0 + rb];
        }
#pragma unroll
        for (int j = 0; j < 4; j++) {
            int col = col0 + wn * 32 + j * 8 + cq * 2;
            if (LAYER == 3) {
                if (va) *reinterpret_cast<float2*>(g_bufA + oa + col) =
                    make_float2(wa * (acc[i][j][0] + bj[j].x), wa * (acc[i][j][1] + bj[j].y));
                if (vb) *reinterpret_cast<float2*>(g_bufA + ob + col) =
                    make_float2(wb * (acc[i][j][2] + bj[j].x), wb * (acc[i][j][3] + bj[j].y));
            } else {
                __nv_bfloat16* dh = (LAYER == 1) ? g_a1hi : g_a2hi;
                __nv_bfloat16* dl = (LAYER == 1) ? g_a1lo : g_a2lo;
                if (va) {
                    float v0 = fmaxf(acc[i][j][0] + bj[j].x, 0.f);
                    float v1 = fmaxf(acc[i][j][1] + bj[j].y, 0.f);
                    __nv_bfloat16 h0, h1, l0, l1;
                    split1(v0, h0, l0); split1(v1, h1, l1);
                    *reinterpret_cast<uint32_t*>(dh + oa + col) = pk(h0, h1);
                    *reinterpret_cast<uint32_t*>(dl + oa + col) = pk(l0, l1);
                }
                if (vb) {
                    float v0 = fmaxf(acc[i][j][2] + bj[j].x, 0.f);
                    float v1 = fmaxf(acc[i][j][3] + bj[j].y, 0.f);
                    __nv_bfloat16 h0, h1, l0, l1;
                    split1(v0, h0, l0); split1(v1, h1, l1);
                    *reinterpret_cast<uint32_t*>(dh + ob + col) = pk(h0, h1);
                    *reinterpret_cast<uint32_t*>(dl + ob + col) = pk(l0, l1);
                }
            }
        }
    }
}

// ---------------- final combine ----------------
__global__ void k_combine(float* __restrict__ out, int T) {
    long i = (long)blockIdx.x * blockDim.x + threadIdx.x;
    long n = (long)T * (H / 4);
    if (i >= n) return;
    int t  = (int)(i / (H / 4));
    int c4 = (int)(i % (H / 4));
    int p0 = g_tok_pos[2 * t], p1 = g_tok_pos[2 * t + 1];
    float4 a = *reinterpret_cast<const float4*>(g_bufA + (size_t)p0 * H + c4 * 4);
    float4 b = *reinterpret_cast<const float4*>(g_bufA + (size_t)p1 * H + c4 * 4);
    *reinterpret_cast<float4*>(out + (size_t)t * H + c4 * 4) =
        make_float4(a.x + b.x, a.y + b.y, a.z + b.z, a.w + b.w);
}

// ---------------- launch ----------------
extern "C" void kernel_launch(void* const* d_in, const int* in_sizes, int n_in,
                              void* d_out, int out_size) {
    const float* x  = (const float*)d_in[0];
    const float* gw = (const float*)d_in[1];
    const float* gb = (const float*)d_in[2];
    const float* w1 = (const float*)d_in[3];
    const float* b1 = (const float*)d_in[4];
    const float* w2 = (const float*)d_in[5];
    const float* b2 = (const float*)d_in[6];
    const float* w3 = (const float*)d_in[7];
    const float* b3 = (const float*)d_in[8];
    float* out = (float*)d_out;

    int T = in_sizes[0] / H;
    if (T > MAXT) T = MAXT;
    long outN = (long)T * H;
    bool has_logits = ((long)out_size >= outN + (long)T * NEXP);
    float* logits = has_logits ? out + outN : nullptr;

    cudaFuncSetAttribute(k_gemm_mma<1>, cudaFuncAttributeMaxDynamicSharedMemorySize, SMEM_TOTAL);
    cudaFuncSetAttribute(k_gemm_mma<2>, cudaFuncAttributeMaxDynamicSharedMemorySize, SMEM_TOTAL);
    cudaFuncSetAttribute(k_gemm_mma<3>, cudaFuncAttributeMaxDynamicSharedMemorySize, SMEM_TOTAL);

    k_init<<<1, 32>>>();

    dim3 tg(32, 32, NEXP), tb(32, 8);
    k_split_w<<<tg, tb>>>(w1, 0);
    k_split_w<<<tg, tb>>>(w2, 1);
    k_split_w<<<tg, tb>>>(w3, 2);
    k_split_x<<<512, 256>>>(x, (long)T * H / 4);

    k_router<<<(T * 32 + 255) / 256, 256>>>(x, gw, gb, logits, T);
    k_offsets<<<1, 32>>>();
    k_scatter<<<(2 * T + 255) / 256, 256>>>(T);

    dim3 grid(H / TILE_N, MAXT / TILE_M, NEXP);   // empty row-tiles early-exit
    k_gemm_mma<1><<<grid, 256, SMEM_TOTAL>>>(0, b1, T);
    k_gemm_mma<2><<<grid, 256, SMEM_TOTAL>>>(1, b2, T);
    k_gemm_mma<3><<<grid, 256, SMEM_TOTAL>>>(2, b3, T);

    long nc = (long)T * (H / 4);
    k_combine<<<(int)((nc + 255) / 256), 256>>>(out, T);
}

// round 4
// speedup vs baseline: 2.1937x; 1.2187x over previous
#include <cuda_runtime.h>
#include <cuda_bf16.h>
#include <math.h>
#include <stdint.h>

#define H     1024
#define NEXP  8
#define MAXT  8192
#define MAXROWS (MAXT * 2)

#define BK      32
#define NK      (H / BK)      // 32 k-tiles
#define TILE_M  128
#define TILE_N  128
#define NSTAGE  2

// SMEM stage layout: 4 buffers of 128 rows x 80B (32 bf16 + 8 pad)
#define ROWB        80
#define BUF_BYTES   (128 * ROWB)        // 10240
#define OFF_AHI     0
#define OFF_ALO     (1 * BUF_BYTES)
#define OFF_BHI     (2 * BUF_BYTES)
#define OFF_BLO     (3 * BUF_BYTES)
#define STAGE_BYTES (4 * BUF_BYTES)     // 40960
#define SMEM_TOTAL  (NSTAGE * STAGE_BYTES)  // 81920 -> 2 CTAs/SM

// ---------------- scratch (device globals; no runtime allocation) ----------------
__device__ float g_bufA[(size_t)MAXROWS * H];                     // 64 MiB (layer3 partials)
__device__ __nv_bfloat16 g_a1hi[(size_t)MAXROWS * H];
__device__ __nv_bfloat16 g_a1lo[(size_t)MAXROWS * H];
__device__ __nv_bfloat16 g_a2hi[(size_t)MAXROWS * H];
__device__ __nv_bfloat16 g_a2lo[(size_t)MAXROWS * H];
__device__ __nv_bfloat16 g_xhi[(size_t)MAXT * H];
__device__ __nv_bfloat16 g_xlo[(size_t)MAXT * H];
__device__ __nv_bfloat16 g_wthi[(size_t)3 * NEXP * H * H];        // [l][e][n][k]
__device__ __nv_bfloat16 g_wtlo[(size_t)3 * NEXP * H * H];
__device__ int   g_cnt[NEXP];
__device__ int   g_off[NEXP];
__device__ int   g_fill[NEXP];
__device__ int   g_row_tok[MAXROWS];
__device__ float g_row_w[MAXROWS];
__device__ int   g_tok_e[MAXROWS];
__device__ float g_tok_w[MAXROWS];
__device__ int   g_tok_pos[MAXROWS];

// ---------------- helpers ----------------
__device__ __forceinline__ uint32_t smem_u32(const void* p) {
    uint32_t a;
    asm("{ .reg .u64 t; cvta.to.shared.u64 t, %1; cvt.u32.u64 %0, t; }" : "=r"(a) : "l"(p));
    return a;
}
__device__ __forceinline__ void cp16(uint32_t dst, const void* src, uint32_t sz) {
    asm volatile("cp.async.cg.shared.global [%0], [%1], 16, %2;"
                 :: "r"(dst), "l"(src), "r"(sz) : "memory");
}
__device__ __forceinline__ void cp_commit() { asm volatile("cp.async.commit_group;" ::: "memory"); }
template <int N>
__device__ __forceinline__ void cp_wait() { asm volatile("cp.async.wait_group %0;" :: "n"(N) : "memory"); }

__device__ __forceinline__ void mma_bf16(float* d, const uint32_t* a, const uint32_t* b) {
    asm volatile("mma.sync.aligned.m16n8k16.row.col.f32.bf16.bf16.f32 "
        "{%0,%1,%2,%3}, {%4,%5,%6,%7}, {%8,%9}, {%0,%1,%2,%3};"
        : "+f"(d[0]), "+f"(d[1]), "+f"(d[2]), "+f"(d[3])
        : "r"(a[0]), "r"(a[1]), "r"(a[2]), "r"(a[3]), "r"(b[0]), "r"(b[1]));
}
__device__ __forceinline__ void ldsm4(uint32_t* r, uint32_t addr) {
    asm volatile("ldmatrix.sync.aligned.m8n8.x4.shared.b16 {%0,%1,%2,%3}, [%4];"
        : "=r"(r[0]), "=r"(r[1]), "=r"(r[2]), "=r"(r[3]) : "r"(addr));
}
__device__ __forceinline__ uint32_t pk(__nv_bfloat16 a, __nv_bfloat16 b) {
    __nv_bfloat162 t = __halves2bfloat162(a, b);
    return *reinterpret_cast<uint32_t*>(&t);
}
__device__ __forceinline__ void split1(float v, __nv_bfloat16& h, __nv_bfloat16& l) {
    h = __float2bfloat16(v);
    l = __float2bfloat16(v - __bfloat162float(h));
}

// ---------------- setup kernels ----------------
// x split (fp32 -> bf16 hi/lo) + expert-count init (block 0)
__global__ void k_split_x(const float* __restrict__ x, long n) {
    if (blockIdx.x == 0 && threadIdx.x < NEXP) g_cnt[threadIdx.x] = 0;
    long i = (long)blockIdx.x * blockDim.x + threadIdx.x;
    long stride = (long)gridDim.x * blockDim.x;
    for (; i < n; i += stride) {
        float4 v = reinterpret_cast<const float4*>(x)[i];
        __nv_bfloat16 h0, h1, h2, h3, l0, l1, l2, l3;
        split1(v.x, h0, l0); split1(v.y, h1, l1);
        split1(v.z, h2, l2); split1(v.w, h3, l3);
        reinterpret_cast<uint2*>(g_xhi)[i] = make_uint2(pk(h0, h1), pk(h2, h3));
        reinterpret_cast<uint2*>(g_xlo)[i] = make_uint2(pk(l0, l1), pk(l2, l3));
    }
}

__global__ void k_offsets() {
    if (threadIdx.x == 0) {
        int s = 0;
        for (int e = 0; e < NEXP; e++) { g_off[e] = s; s += g_cnt[e]; g_fill[e] = 0; }
    }
}

__global__ void k_scatter(int T) {
    int i = blockIdx.x * blockDim.x + threadIdx.x;
    if (i >= 2 * T) return;
    int e = g_tok_e[i];
    int pos = g_off[e] + atomicAdd(&g_fill[e], 1);
    g_row_tok[pos] = i >> 1;
    g_row_w[pos]   = g_tok_w[i];
    g_tok_pos[i]   = pos;
}

// ---------------- router ----------------
__global__ void k_router(const float* __restrict__ x, const float* __restrict__ gw,
                         const float* __restrict__ gb, float* __restrict__ logits_out, int T) {
    int warp = (blockIdx.x * blockDim.x + threadIdx.x) >> 5;
    int lane = threadIdx.x & 31;
    if (warp >= T) return;
    const float* xr = x + (size_t)warp * H;

    float acc[NEXP];
#pragma unroll
    for (int e = 0; e < NEXP; e++) acc[e] = 0.f;
    for (int h = lane; h < H; h += 32) {
        float xv = __ldg(xr + h);
        const float4* g = reinterpret_cast<const float4*>(gw + (size_t)h * NEXP);
        float4 a = __ldg(g); float4 b = __ldg(g + 1);
        acc[0] += xv * a.x; acc[1] += xv * a.y; acc[2] += xv * a.z; acc[3] += xv * a.w;
        acc[4] += xv * b.x; acc[5] += xv * b.y; acc[6] += xv * b.z; acc[7] += xv * b.w;
    }
#pragma unroll
    for (int e = 0; e < NEXP; e++)
#pragma unroll
        for (int o = 16; o > 0; o >>= 1)
            acc[e] += __shfl_xor_sync(0xffffffffu, acc[e], o);

    if (lane == 0) {
        float lg[NEXP];
#pragma unroll
        for (int e = 0; e < NEXP; e++) {
            lg[e] = acc[e] + gb[e];
            if (logits_out) logits_out[(size_t)warp * NEXP + e] = lg[e];
        }
        int i1 = 0;
#pragma unroll
        for (int e = 1; e < NEXP; e++) if (lg[e] > lg[i1]) i1 = e;
        int i2 = (i1 == 0) ? 1 : 0;
#pragma unroll
        for (int e = 0; e < NEXP; e++) { if (e == i1) continue; if (lg[e] > lg[i2]) i2 = e; }
        float p2 = expf(lg[i2] - lg[i1]);
        float inv = 1.f / (1.f + p2);
        g_tok_e[warp * 2 + 0] = i1; g_tok_w[warp * 2 + 0] = inv;
        g_tok_e[warp * 2 + 1] = i2; g_tok_w[warp * 2 + 1] = p2 * inv;
        atomicAdd(&g_cnt[i1], 1);
        atomicAdd(&g_cnt[i2], 1);
    }
}

// ---------------- fused weight transpose + bf16 hi/lo split (all 3 layers) ----------------
__global__ void k_split_w3(const float* __restrict__ w1, const float* __restrict__ w2,
                           const float* __restrict__ w3) {
    __shared__ float t[32][33];
    int lz = blockIdx.z;
    int layer = lz >> 3, e = lz & 7;
    const float* W = (layer == 0) ? w1 : ((layer == 1) ? w2 : w3);
    int kb = blockIdx.y * 32, nb = blockIdx.x * 32;
    const float* We = W + (size_t)e * H * H;
    int tx = threadIdx.x, ty = threadIdx.y;   // 32 x 8
#pragma unroll
    for (int i = 0; i < 32; i += 8)
        t[ty + i][tx] = We[(size_t)(kb + ty + i) * H + nb + tx];
    __syncthreads();
    size_t obase = ((size_t)layer * NEXP + e) * H * H;
    __nv_bfloat16* he = g_wthi + obase;
    __nv_bfloat16* le = g_wtlo + obase;
#pragma unroll
    for (int i = 0; i < 32; i += 8) {
        float v = t[tx][ty + i];
        __nv_bfloat16 h, l; split1(v, h, l);
        he[(size_t)(nb + ty + i) * H + kb + tx] = h;
        le[(size_t)(nb + ty + i) * H + kb + tx] = l;
    }
}

// ---------------- HMMA split-bf16 gathered expert GEMM ----------------
template <int LAYER>
__global__ __launch_bounds__(256, 2)
void k_gemm_mma(int layer, const float* __restrict__ Bias, int T) {
    int e = blockIdx.z;
    int cnt = g_cnt[e];
    int row0 = blockIdx.y * TILE_M;
    if (row0 >= cnt) return;
    int base = g_off[e];
    int col0 = blockIdx.x * TILE_N;
    int tid = threadIdx.x;
    int wid = tid >> 5, lane = tid & 31;
    int wm = wid & 1, wn = wid >> 1;       // warp tile: rows wm*64, cols wn*32
    int r1 = lane >> 2, cq = lane & 3;

    extern __shared__ char smem[];
    uint32_t sb = smem_u32(smem);

    // ---- per-thread load setup ----
    int lrow = tid >> 1, lhalf = tid & 1;   // 2 threads per row, 32B halves
    int agrow = row0 + lrow;
    bool aval = (agrow < cnt);
    long aridx = 0;
    if (aval) aridx = (LAYER == 1) ? (long)g_row_tok[base + agrow] : (long)(base + agrow);
    const __nv_bfloat16* pAhi;
    const __nv_bfloat16* pAlo;
    if (LAYER == 1)      { pAhi = g_xhi;  pAlo = g_xlo;  }
    else if (LAYER == 2) { pAhi = g_a1hi; pAlo = g_a1lo; }
    else                 { pAhi = g_a2hi; pAlo = g_a2lo; }
    const char* gAhi = (const char*)(pAhi + (size_t)aridx * H) + lhalf * 32;
    const char* gAlo = (const char*)(pAlo + (size_t)aridx * H) + lhalf * 32;
    uint32_t aSz = aval ? 16u : 0u;   // cp.async zero-fills when src-size 0

    size_t wbase = ((size_t)layer * NEXP + e) * H * H;
    const char* gBhi = (const char*)(g_wthi + wbase + (size_t)(col0 + lrow) * H) + lhalf * 32;
    const char* gBlo = (const char*)(g_wtlo + wbase + (size_t)(col0 + lrow) * H) + lhalf * 32;

    uint32_t sdst = sb + lrow * ROWB + lhalf * 32;

    // ldmatrix per-thread row offsets
    int lg = lane >> 3, lr = lane & 7;
    uint32_t aRowOff = (uint32_t)((((lg & 1) << 3) + lr) * ROWB + ((lg >> 1) << 4));
    uint32_t bRowOff = (uint32_t)((((lg >> 1) << 3) + lr) * ROWB + ((lg & 1) << 4));
    uint32_t aBase = (uint32_t)(wm * 64) * ROWB + aRowOff;   // + i*16*ROWB + kb
    uint32_t bBase = (uint32_t)(wn * 32) * ROWB + bRowOff;   // + jp*16*ROWB + kb

    // ---- accumulators ----
    float acc[4][4][4];
#pragma unroll
    for (int i = 0; i < 4; i++)
#pragma unroll
        for (int j = 0; j < 4; j++)
#pragma unroll
            for (int r = 0; r < 4; r++) acc[i][j][r] = 0.f;

    auto loadStage = [&](int kt) {
        uint32_t st = sdst + (kt & 1) * STAGE_BYTES;
        long go = (long)kt * 64;           // bytes into row
        cp16(st + OFF_AHI,      gAhi + go,      aSz);
        cp16(st + OFF_AHI + 16, gAhi + go + 16, aSz);
        cp16(st + OFF_ALO,      gAlo + go,      aSz);
        cp16(st + OFF_ALO + 16, gAlo + go + 16, aSz);
        cp16(st + OFF_BHI,      gBhi + go,      16u);
        cp16(st + OFF_BHI + 16, gBhi + go + 16, 16u);
        cp16(st + OFF_BLO,      gBlo + go,      16u);
        cp16(st + OFF_BLO + 16, gBlo + go + 16, 16u);
    };

    loadStage(0); cp_commit();

    for (int kt = 0; kt < NK; kt++) {
        cp_wait<0>();
        __syncthreads();
        if (kt + 1 < NK) { loadStage(kt + 1); cp_commit(); }

        uint32_t st = sb + (kt & 1) * STAGE_BYTES;
        uint32_t sAh = st + OFF_AHI + aBase;
        uint32_t sAl = st + OFF_ALO + aBase;
        uint32_t sBh = st + OFF_BHI + bBase;
        uint32_t sBl = st + OFF_BLO + bBase;

#pragma unroll
        for (int kp = 0; kp < 2; kp++) {
            uint32_t kb = kp * 32;
            uint32_t bhi[8], blo[8];               // [j][2] for j=0..3
            ldsm4(bhi + 0, sBh + kb);
            ldsm4(bhi + 4, sBh + kb + 16 * ROWB);
            ldsm4(blo + 0, sBl + kb);
            ldsm4(blo + 4, sBl + kb + 16 * ROWB);
#pragma unroll
            for (int i = 0; i < 4; i++) {
                uint32_t ahi[4], alo[4];
                ldsm4(ahi, sAh + kb + i * (16 * ROWB));
                ldsm4(alo, sAl + kb + i * (16 * ROWB));
#pragma unroll
                for (int j = 0; j < 4; j++) {
                    mma_bf16(acc[i][j], ahi, bhi + 2 * j);
                    mma_bf16(acc[i][j], ahi, blo + 2 * j);
                    mma_bf16(acc[i][j], alo, bhi + 2 * j);
                }
            }
        }
        __syncthreads();   // protect stage kt before iter kt+1's overwrite of slot kt+1... (reuse window)
    }

    // ---- epilogue ----
    const float* be = Bias + (size_t)e * H + col0 + wn * 32 + cq * 2;
    float2 bj[4];
#pragma unroll
    for (int j = 0; j < 4; j++) bj[j] = *reinterpret_cast<const float2*>(be + j * 8);

#pragma unroll
    for (int i = 0; i < 4; i++) {
        int ra = wm * 64 + i * 16 + r1;
        int rb = ra + 8;
        bool va = (row0 + ra < cnt), vb = (row0 + rb < cnt);
        long oa = (long)(base + row0 + ra) * H;
        long ob = (long)(base + row0 + rb) * H;
        float wa = 0.f, wb = 0.f;
        if (LAYER == 3) {
            if (va) wa = g_row_w[base + row0 + ra];
            if (vb) wb = g_row_w[base + row0 + rb];
        }
#pragma unroll
        for (int j = 0; j < 4; j++) {
            int col = col0 + wn * 32 + j * 8 + cq * 2;
            if (LAYER == 3) {
                if (va) *reinterpret_cast<float2*>(g_bufA + oa + col) =
                    make_float2(wa * (acc[i][j][0] + bj[j].x), wa * (acc[i][j][1] + bj[j].y));
                if (vb) *reinterpret_cast<float2*>(g_bufA + ob + col) =
                    make_float2(wb * (acc[i][j][2] + bj[j].x), wb * (acc[i][j][3] + bj[j].y));
            } else {
                __nv_bfloat16* dh = (LAYER == 1) ? g_a1hi : g_a2hi;
                __nv_bfloat16* dl = (LAYER == 1) ? g_a1lo : g_a2lo;
                if (va) {
                    float v0 = fmaxf(acc[i][j][0] + bj[j].x, 0.f);
                    float v1 = fmaxf(acc[i][j][1] + bj[j].y, 0.f);
                    __nv_bfloat16 h0, h1, l0, l1;
                    split1(v0, h0, l0); split1(v1, h1, l1);
                    *reinterpret_cast<uint32_t*>(dh + oa + col) = pk(h0, h1);
                    *reinterpret_cast<uint32_t*>(dl + oa + col) = pk(l0, l1);
                }
                if (vb) {
                    float v0 = fmaxf(acc[i][j][2] + bj[j].x, 0.f);
                    float v1 = fmaxf(acc[i][j][3] + bj[j].y, 0.f);
                    __nv_bfloat16 h0, h1, l0, l1;
                    split1(v0, h0, l0); split1(v1, h1, l1);
                    *reinterpret_cast<uint32_t*>(dh + ob + col) = pk(h0, h1);
                    *reinterpret_cast<uint32_t*>(dl + ob + col) = pk(l0, l1);
                }
            }
        }
    }
}

// ---------------- final combine ----------------
__global__ void k_combine(float* __restrict__ out, int T) {
    long i = (long)blockIdx.x * blockDim.x + threadIdx.x;
    long n = (long)T * (H / 4);
    if (i >= n) return;
    int t  = (int)(i / (H / 4));
    int c4 = (int)(i % (H / 4));
    int p0 = g_tok_pos[2 * t], p1 = g_tok_pos[2 * t + 1];
    float4 a = *reinterpret_cast<const float4*>(g_bufA + (size_t)p0 * H + c4 * 4);
    float4 b = *reinterpret_cast<const float4*>(g_bufA + (size_t)p1 * H + c4 * 4);
    *reinterpret_cast<float4*>(out + (size_t)t * H + c4 * 4) =
        make_float4(a.x + b.x, a.y + b.y, a.z + b.z, a.w + b.w);
}

// ---------------- launch ----------------
// Launch order puts k_gemm_mma<1> at launch index 5 so the ncu -s 5 -c 1
// window captures a GEMM (the kernel that matters) instead of setup.
extern "C" void kernel_launch(void* const* d_in, const int* in_sizes, int n_in,
                              void* d_out, int out_size) {
    const float* x  = (const float*)d_in[0];
    const float* gw = (const float*)d_in[1];
    const float* gb = (const float*)d_in[2];
    const float* w1 = (const float*)d_in[3];
    const float* b1 = (const float*)d_in[4];
    const float* w2 = (const float*)d_in[5];
    const float* b2 = (const float*)d_in[6];
    const float* w3 = (const float*)d_in[7];
    const float* b3 = (const float*)d_in[8];
    float* out = (float*)d_out;

    int T = in_sizes[0] / H;
    if (T > MAXT) T = MAXT;
    long outN = (long)T * H;
    bool has_logits = ((long)out_size >= outN + (long)T * NEXP);
    float* logits = has_logits ? out + outN : nullptr;

    cudaFuncSetAttribute(k_gemm_mma<1>, cudaFuncAttributeMaxDynamicSharedMemorySize, SMEM_TOTAL);
    cudaFuncSetAttribute(k_gemm_mma<2>, cudaFuncAttributeMaxDynamicSharedMemorySize, SMEM_TOTAL);
    cudaFuncSetAttribute(k_gemm_mma<3>, cudaFuncAttributeMaxDynamicSharedMemorySize, SMEM_TOTAL);

    k_split_x<<<512, 256>>>(x, (long)T * H / 4);                       // #0 (also zeroes g_cnt)
    k_router<<<(T * 32 + 255) / 256, 256>>>(x, gw, gb, logits, T);     // #1
    k_offsets<<<1, 32>>>();                                            // #2
    k_scatter<<<(2 * T + 255) / 256, 256>>>(T);                        // #3
    dim3 tg(32, 32, 3 * NEXP), tb(32, 8);
    k_split_w3<<<tg, tb>>>(w1, w2, w3);                                // #4

    dim3 grid(H / TILE_N, MAXT / TILE_M, NEXP);
    k_gemm_mma<1><<<grid, 256, SMEM_TOTAL>>>(0, b1, T);                // #5  <- ncu capture
    k_gemm_mma<2><<<grid, 256, SMEM_TOTAL>>>(1, b2, T);                // #6
    k_gemm_mma<3><<<grid, 256, SMEM_TOTAL>>>(2, b3, T);                // #7

    long nc = (long)T * (H / 4);
    k_combine<<<(int)((nc + 255) / 256), 256>>>(out, T);               // #8
}

// round 7
// speedup vs baseline: 3.3136x; 1.5105x over previous
#include <cuda_runtime.h>
#include <cuda_fp16.h>
#include <math.h>
#include <stdint.h>

#define H     1024
#define NEXP  8
#define MAXT  8192
#define MAXROWS (MAXT * 2)

#define BK      32
#define NK      (H / BK)      // 32 k-tiles
#define TILE_M  128
#define TILE_N  128

// SMEM stage layout: 3 buffers of 128 rows x 80B (32 fp16 + 16B pad)
#define ROWB        80
#define BUF_BYTES   (128 * ROWB)        // 10240
#define OFF_A       0
#define OFF_BHI     (1 * BUF_BYTES)
#define OFF_BLO     (2 * BUF_BYTES)
#define STAGE_BYTES (3 * BUF_BYTES)     // 30720
#define SMEM_TOTAL  (2 * STAGE_BYTES)   // 61440 -> 2 CTAs/SM

// ---------------- scratch (device globals; no runtime allocation) ----------------
__device__ float  g_bufA[(size_t)MAXROWS * H];          // layer3 weighted partials
__device__ __half g_a1[(size_t)MAXROWS * H];            // layer1 out (fp16)
__device__ __half g_a2[(size_t)MAXROWS * H];            // layer2 out (fp16)
__device__ __half g_xh[(size_t)MAXT * H];               // x in fp16
__device__ __half g_wthi[(size_t)3 * NEXP * H * H];     // [l][e][n][k] fp16 hi
__device__ __half g_wtlo[(size_t)3 * NEXP * H * H];     // fp16 lo
__device__ int   g_cnt[NEXP];
__device__ int   g_off[NEXP];
__device__ int   g_fill[NEXP];
__device__ int   g_done;
__device__ int   g_row_tok[MAXROWS];
__device__ float g_row_w[MAXROWS];
__device__ int   g_tok_pos[MAXROWS];

// ---------------- helpers ----------------
__device__ __forceinline__ uint32_t smem_u32(const void* p) {
    uint32_t a;
    asm("{ .reg .u64 t; cvta.to.shared.u64 t, %1; cvt.u32.u64 %0, t; }" : "=r"(a) : "l"(p));
    return a;
}
__device__ __forceinline__ void cp16(uint32_t dst, const void* src, uint32_t sz) {
    asm volatile("cp.async.cg.shared.global [%0], [%1], 16, %2;"
                 :: "r"(dst), "l"(src), "r"(sz) : "memory");
}
__device__ __forceinline__ void cp_commit() { asm volatile("cp.async.commit_group;" ::: "memory"); }
template <int N>
__device__ __forceinline__ void cp_wait() { asm volatile("cp.async.wait_group %0;" :: "n"(N) : "memory"); }

__device__ __forceinline__ void mma_f16(float* d, const uint32_t* a, const uint32_t* b) {
    asm volatile("mma.sync.aligned.m16n8k16.row.col.f32.f16.f16.f32 "
        "{%0,%1,%2,%3}, {%4,%5,%6,%7}, {%8,%9}, {%0,%1,%2,%3};"
        : "+f"(d[0]), "+f"(d[1]), "+f"(d[2]), "+f"(d[3])
        : "r"(a[0]), "r"(a[1]), "r"(a[2]), "r"(a[3]), "r"(b[0]), "r"(b[1]));
}
__device__ __forceinline__ void ldsm4(uint32_t* r, uint32_t addr) {
    asm volatile("ldmatrix.sync.aligned.m8n8.x4.shared.b16 {%0,%1,%2,%3}, [%4];"
        : "=r"(r[0]), "=r"(r[1]), "=r"(r[2]), "=r"(r[3]) : "r"(addr));
}
__device__ __forceinline__ uint32_t pkh(__half a, __half b) {
    __half2 t = __halves2half2(a, b);
    return *reinterpret_cast<uint32_t*>(&t);
}
__device__ __forceinline__ void split1h(float v, __half& h, __half& l) {
    h = __float2half(v);
    l = __float2half(v - __half2float(h));
}

// ---------------- router: logits, top-2, x->fp16, tail offsets ----------------
__global__ void k_router(const float* __restrict__ x, const float* __restrict__ gw,
                         const float* __restrict__ gb, float* __restrict__ logits_out, int T) {
    int warp = (blockIdx.x * blockDim.x + threadIdx.x) >> 5;
    int lane = threadIdx.x & 31;
    if (warp < T) {
        const float* xr = x + (size_t)warp * H;
        float acc[NEXP];
#pragma unroll
        for (int e = 0; e < NEXP; e++) acc[e] = 0.f;
        for (int h = lane * 2; h < H; h += 64) {
            float2 xv = *reinterpret_cast<const float2*>(xr + h);
            const float4* g0 = reinterpret_cast<const float4*>(gw + (size_t)h * NEXP);
            float4 a = __ldg(g0), b = __ldg(g0 + 1), c = __ldg(g0 + 2), d = __ldg(g0 + 3);
            acc[0] += xv.x * a.x + xv.y * c.x;  acc[1] += xv.x * a.y + xv.y * c.y;
            acc[2] += xv.x * a.z + xv.y * c.z;  acc[3] += xv.x * a.w + xv.y * c.w;
            acc[4] += xv.x * b.x + xv.y * d.x;  acc[5] += xv.x * b.y + xv.y * d.y;
            acc[6] += xv.x * b.z + xv.y * d.z;  acc[7] += xv.x * b.w + xv.y * d.w;
            *reinterpret_cast<uint32_t*>(g_xh + (size_t)warp * H + h) =
                pkh(__float2half(xv.x), __float2half(xv.y));
        }
#pragma unroll
        for (int e = 0; e < NEXP; e++)
#pragma unroll
            for (int o = 16; o > 0; o >>= 1)
                acc[e] += __shfl_xor_sync(0xffffffffu, acc[e], o);

        if (lane == 0) {
            float lg[NEXP];
#pragma unroll
            for (int e = 0; e < NEXP; e++) {
                lg[e] = acc[e] + gb[e];
                if (logits_out) logits_out[(size_t)warp * NEXP + e] = lg[e];
            }
            int i1 = 0;
#pragma unroll
            for (int e = 1; e < NEXP; e++) if (lg[e] > lg[i1]) i1 = e;
            int i2 = (i1 == 0) ? 1 : 0;
#pragma unroll
            for (int e = 0; e < NEXP; e++) { if (e == i1) continue; if (lg[e] > lg[i2]) i2 = e; }
            float p2 = expf(lg[i2] - lg[i1]);
            float inv = 1.f / (1.f + p2);
            // pack (expert, weight) for scatter
            g_row_tok[warp * 2 + 0] = i1;       // temporarily expert ids (scatter rewrites)
            g_row_tok[warp * 2 + 1] = i2;
            g_row_w[warp * 2 + 0] = inv;        // temporarily per-(tok,k) weights
            g_row_w[warp * 2 + 1] = p2 * inv;
            atomicAdd(&g_cnt[i1], 1);
            atomicAdd(&g_cnt[i2], 1);
        }
    }
    // ---- tail: last block computes expert offsets ----
    __threadfence();
    __syncthreads();
    if (threadIdx.x == 0) {
        int ticket = atomicAdd(&g_done, 1);
        if (ticket == (int)gridDim.x - 1) {
            int s = 0;
#pragma unroll
            for (int e = 0; e < NEXP; e++) { g_off[e] = s; s += g_cnt[e]; g_fill[e] = 0; }
            g_done = 0;
            __threadfence();
        }
    }
}

// NOTE: router stored expert ids in g_row_tok[] and weights in g_row_w[] keyed by (token,k).
// k_scatter converts to gathered-row layout; it reads before writing the same slot only
// when pos == i, which is value-identical.
__device__ int   g_tmp_e[MAXROWS];
__device__ float g_tmp_w[MAXROWS];

__global__ void k_scatter(int T) {
    int i = blockIdx.x * blockDim.x + threadIdx.x;
    if (i >= 2 * T) return;
    // copy to temps first is not needed across kernels; but within this kernel slot reuse
    // of g_row_tok/g_row_w is racy. Use separate temp arrays written by router? Simpler:
    // read my own slot, then scatter into the temp arrays, gemm reads temps.
    int e = g_row_tok[i];
    float w = g_row_w[i];
    int pos = g_off[e] + atomicAdd(&g_fill[e], 1);
    g_tmp_e[pos] = i >> 1;     // token index, gathered order
    g_tmp_w[pos] = w;
    g_tok_pos[i] = pos;
}

// ---------------- fused weight transpose + fp16 hi/lo split (all 3 layers) ----------------
__global__ void k_split_w3(const float* __restrict__ w1, const float* __restrict__ w2,
                           const float* __restrict__ w3) {
    __shared__ float t[32][33];
    int lz = blockIdx.z;
    int layer = lz >> 3, e = lz & 7;
    const float* W = (layer == 0) ? w1 : ((layer == 1) ? w2 : w3);
    int kb = blockIdx.y * 32, nb = blockIdx.x * 32;
    const float* We = W + (size_t)e * H * H;
    int tx = threadIdx.x, ty = threadIdx.y;   // 32 x 8
#pragma unroll
    for (int i = 0; i < 32; i += 8)
        t[ty + i][tx] = We[(size_t)(kb + ty + i) * H + nb + tx];
    __syncthreads();
    size_t obase = ((size_t)layer * NEXP + e) * H * H;
    __half* he = g_wthi + obase;
    __half* le = g_wtlo + obase;
#pragma unroll
    for (int i = 0; i < 32; i += 8) {
        float v = t[tx][ty + i];
        __half h, l; split1h(v, h, l);
        he[(size_t)(nb + ty + i) * H + kb + tx] = h;
        le[(size_t)(nb + ty + i) * H + kb + tx] = l;
    }
}

// ---------------- HMMA 2-pass fp16 gathered expert GEMM ----------------
// D = A_fp16 * (Bhi + Blo),  B split carries 22 bits; error = A fp16 rounding only.
// LAYER 1: A = g_xh gathered -> relu -> g_a1
// LAYER 2: A = g_a1          -> relu -> g_a2
// LAYER 3: A = g_a2          -> w*(acc+bias) -> g_bufA fp32
template <int LAYER>
__global__ __launch_bounds__(256, 2)
void k_gemm_mma(int layer, const float* __restrict__ Bias, int T) {
    int e = blockIdx.z;
    int cnt = g_cnt[e];
    int row0 = blockIdx.y * TILE_M;
    if (row0 >= cnt) return;
    int base = g_off[e];
    int col0 = blockIdx.x * TILE_N;
    int tid = threadIdx.x;
    int wid = tid >> 5, lane = tid & 31;
    int wm = wid & 1, wn = wid >> 1;       // warp tile: rows wm*64, cols wn*32
    int r1 = lane >> 2, cq = lane & 3;

    extern __shared__ char smem[];
    uint32_t sb = smem_u32(smem);

    // ---- per-thread load setup (2 threads per row, 32B halves) ----
    int lrow = tid >> 1, lhalf = tid & 1;
    int agrow = row0 + lrow;
    bool aval = (agrow < cnt);
    long aridx = 0;
    if (aval) aridx = (LAYER == 1) ? (long)g_tmp_e[base + agrow] : (long)(base + agrow);
    const __half* pA = (LAYER == 1) ? g_xh : ((LAYER == 2) ? g_a1 : g_a2);
    const char* gA = (const char*)(pA + (size_t)aridx * H) + lhalf * 32;
    uint32_t aSz = aval ? 16u : 0u;   // src-size 0 => zero-fill

    size_t wbase = ((size_t)layer * NEXP + e) * H * H;
    const char* gBhi = (const char*)(g_wthi + wbase + (size_t)(col0 + lrow) * H) + lhalf * 32;
    const char* gBlo = (const char*)(g_wtlo + wbase + (size_t)(col0 + lrow) * H) + lhalf * 32;

    uint32_t sdst = sb + lrow * ROWB + lhalf * 32;

    // ldmatrix per-thread row offsets
    int lg = lane >> 3, lr = lane & 7;
    uint32_t aRowOff = (uint32_t)((((lg & 1) << 3) + lr) * ROWB + ((lg >> 1) << 4));
    uint32_t bRowOff = (uint32_t)((((lg >> 1) << 3) + lr) * ROWB + ((lg & 1) << 4));
    uint32_t aBase = (uint32_t)(wm * 64) * ROWB + aRowOff;
    uint32_t bBase = (uint32_t)(wn * 32) * ROWB + bRowOff;

    float acc[4][4][4];
#pragma unroll
    for (int i = 0; i < 4; i++)
#pragma unroll
        for (int j = 0; j < 4; j++)
#pragma unroll
            for (int r = 0; r < 4; r++) acc[i][j][r] = 0.f;

    auto loadStage = [&](int kt) {
        uint32_t st = sdst + (kt & 1) * STAGE_BYTES;
        long go = (long)kt * 64;           // bytes into row (BK fp16)
        cp16(st + OFF_A,        gA + go,        aSz);
        cp16(st + OFF_A + 16,   gA + go + 16,   aSz);
        cp16(st + OFF_BHI,      gBhi + go,      16u);
        cp16(st + OFF_BHI + 16, gBhi + go + 16, 16u);
        cp16(st + OFF_BLO,      gBlo + go,      16u);
        cp16(st + OFF_BLO + 16, gBlo + go + 16, 16u);
    };

    loadStage(0); cp_commit();

    for (int kt = 0; kt < NK; kt++) {
        cp_wait<0>();
        __syncthreads();
        if (kt + 1 < NK) { loadStage(kt + 1); cp_commit(); }

        uint32_t st = sb + (kt & 1) * STAGE_BYTES;
        uint32_t sA  = st + OFF_A   + aBase;
        uint32_t sBh = st + OFF_BHI + bBase;
        uint32_t sBl = st + OFF_BLO + bBase;

#pragma unroll
        for (int kp = 0; kp < 2; kp++) {
            uint32_t kb = kp * 32;
            uint32_t bhi[8], blo[8];
            ldsm4(bhi + 0, sBh + kb);
            ldsm4(bhi + 4, sBh + kb + 16 * ROWB);
            ldsm4(blo + 0, sBl + kb);
            ldsm4(blo + 4, sBl + kb + 16 * ROWB);
#pragma unroll
            for (int i = 0; i < 4; i++) {
                uint32_t a[4];
                ldsm4(a, sA + kb + i * (16 * ROWB));
#pragma unroll
                for (int j = 0; j < 4; j++) {
                    mma_f16(acc[i][j], a, bhi + 2 * j);
                    mma_f16(acc[i][j], a, blo + 2 * j);
                }
            }
        }
        __syncthreads();
    }

    // ---- epilogue ----
    const float* be = Bias + (size_t)e * H + col0 + wn * 32 + cq * 2;
    float2 bj[4];
#pragma unroll
    for (int j = 0; j < 4; j++) bj[j] = *reinterpret_cast<const float2*>(be + j * 8);

#pragma unroll
    for (int i = 0; i < 4; i++) {
        int ra = wm * 64 + i * 16 + r1;
        int rb = ra + 8;
        bool va = (row0 + ra < cnt), vb = (row0 + rb < cnt);
        long oa = (long)(base + row0 + ra) * H;
        long ob = (long)(base + row0 + rb) * H;
        float wa = 0.f, wb = 0.f;
        if (LAYER == 3) {
            if (va) wa = g_tmp_w[base + row0 + ra];
            if (vb) wb = g_tmp_w[base + row0 + rb];
        }
#pragma unroll
        for (int j = 0; j < 4; j++) {
            int col = col0 + wn * 32 + j * 8 + cq * 2;
            if (LAYER == 3) {
                if (va) *reinterpret_cast<float2*>(g_bufA + oa + col) =
                    make_float2(wa * (acc[i][j][0] + bj[j].x), wa * (acc[i][j][1] + bj[j].y));
                if (vb) *reinterpret_cast<float2*>(g_bufA + ob + col) =
                    make_float2(wb * (acc[i][j][2] + bj[j].x), wb * (acc[i][j][3] + bj[j].y));
            } else {
                __half* dh = (LAYER == 1) ? g_a1 : g_a2;
                if (va) {
                    float v0 = fmaxf(acc[i][j][0] + bj[j].x, 0.f);
                    float v1 = fmaxf(acc[i][j][1] + bj[j].y, 0.f);
                    *reinterpret_cast<uint32_t*>(dh + oa + col) =
                        pkh(__float2half(v0), __float2half(v1));
                }
                if (vb) {
                    float v0 = fmaxf(acc[i][j][2] + bj[j].x, 0.f);
                    float v1 = fmaxf(acc[i][j][3] + bj[j].y, 0.f);
                    *reinterpret_cast<uint32_t*>(dh + ob + col) =
                        pkh(__float2half(v0), __float2half(v1));
                }
            }
        }
    }
}

// ---------------- final combine (+ counter reset for next replay) ----------------
__global__ void k_combine(float* __restrict__ out, int T) {
    if (blockIdx.x == 0 && threadIdx.x < NEXP) g_cnt[threadIdx.x] = 0;
    long i = (long)blockIdx.x * blockDim.x + threadIdx.x;
    long n = (long)T * (H / 4);
    if (i >= n) return;
    int t  = (int)(i / (H / 4));
    int c4 = (int)(i % (H / 4));
    int p0 = g_tok_pos[2 * t], p1 = g_tok_pos[2 * t + 1];
    float4 a = *reinterpret_cast<const float4*>(g_bufA + (size_t)p0 * H + c4 * 4);
    float4 b = *reinterpret_cast<const float4*>(g_bufA + (size_t)p1 * H + c4 * 4);
    *reinterpret_cast<float4*>(out + (size_t)t * H + c4 * 4) =
        make_float4(a.x + b.x, a.y + b.y, a.z + b.z, a.w + b.w);
}

// ---------------- launch ----------------
// The ncu capture window has landed on launch index 3 every round; order below
// puts k_gemm_mma<1> there so we finally profile the dominant kernel.
extern "C" void kernel_launch(void* const* d_in, const int* in_sizes, int n_in,
                              void* d_out, int out_size) {
    const float* x  = (const float*)d_in[0];
    const float* gw = (const float*)d_in[1];
    const float* gb = (const float*)d_in[2];
    const float* w1 = (const float*)d_in[3];
    const float* b1 = (const float*)d_in[4];
    const float* w2 = (const float*)d_in[5];
    const float* b2 = (const float*)d_in[6];
    const float* w3 = (const float*)d_in[7];
    const float* b3 = (const float*)d_in[8];
    float* out = (float*)d_out;

    int T = in_sizes[0] / H;
    if (T > MAXT) T = MAXT;
    long outN = (long)T * H;
    bool has_logits = ((long)out_size >= outN + (long)T * NEXP);
    float* logits = has_logits ? out + outN : nullptr;

    cudaFuncSetAttribute(k_gemm_mma<1>, cudaFuncAttributeMaxDynamicSharedMemorySize, SMEM_TOTAL);
    cudaFuncSetAttribute(k_gemm_mma<2>, cudaFuncAttributeMaxDynamicSharedMemorySize, SMEM_TOTAL);
    cudaFuncSetAttribute(k_gemm_mma<3>, cudaFuncAttributeMaxDynamicSharedMemorySize, SMEM_TOTAL);

    k_router<<<(T * 32 + 255) / 256, 256>>>(x, gw, gb, logits, T);     // #0 (logits, x->fp16, offsets tail)
    k_scatter<<<(2 * T + 255) / 256, 256>>>(T);                        // #1
    dim3 tg(32, 32, 3 * NEXP), tb(32, 8);
    k_split_w3<<<tg, tb>>>(w1, w2, w3);                                // #2

    dim3 grid(H / TILE_N, MAXT / TILE_M, NEXP);
    k_gemm_mma<1><<<grid, 256, SMEM_TOTAL>>>(0, b1, T);                // #3  <- ncu capture
    k_gemm_mma<2><<<grid, 256, SMEM_TOTAL>>>(1, b2, T);                // #4
    k_gemm_mma<3><<<grid, 256, SMEM_TOTAL>>>(2, b3, T);                // #5

    long nc = (long)T * (H / 4);
    k_combine<<<(int)((nc + 255) / 256), 256>>>(out, T);               // #6 (also resets g_cnt)
}